// round 6
// baseline (speedup 1.0000x reference)
#include <cuda_runtime.h>
#include <math.h>

#define NNODES 20000
#define NEDGES 320000
#define NGRAPH 64

// ---------------- scratch (static device globals; no runtime alloc) ----------------
__device__ float g_bufH[NNODES * 256];   // GEMM output h (pre-aggregation)
__device__ float g_bufA[NNODES * 256];   // layer activations (post edge+ELU)
__device__ float g_bufX[NNODES * 128];   // layer-3 output (set2set input)
__device__ float g_sd[NNODES * 8];       // per-node attention scalars (s|d per head)
__device__ int   g_deg[NNODES];
__device__ int   g_rowptr[NNODES + 1];
__device__ int   g_cursor[NNODES];
__device__ int   g_csr[NEDGES];
__device__ int   g_gptr[NGRAPH + 1];
__device__ float g_qstar[NGRAPH * 256];
__device__ float g_hl[NGRAPH * 128];
__device__ float g_cl[NGRAPH * 128];
__device__ float g_ebuf[NNODES];

// ---------------- init ----------------
__global__ void init_kernel(int* deg, float* qs, float* hl, float* cl, int n) {
    int i = blockIdx.x * blockDim.x + threadIdx.x;
    if (i < n) deg[i] = 0;
    if (i < NGRAPH * 256) qs[i] = 0.f;
    if (i < NGRAPH * 128) { hl[i] = 0.f; cl[i] = 0.f; }
}

// ---------------- CSR build ----------------
__global__ void hist_kernel(const int* __restrict__ dst, int E, int* deg) {
    int i = blockIdx.x * blockDim.x + threadIdx.x;
    if (i < E) atomicAdd(&deg[dst[i]], 1);
}

__global__ void scan_kernel(const int* __restrict__ deg, int* rowptr, int* cursor, int n) {
    __shared__ int part[1024];
    int t = threadIdx.x;
    int CH = (n + 1023) / 1024;
    int base = t * CH;
    int s = 0;
    for (int i = 0; i < CH; i++) { int idx = base + i; if (idx < n) s += deg[idx]; }
    part[t] = s;
    __syncthreads();
    for (int off = 1; off < 1024; off <<= 1) {
        int v = (t >= off) ? part[t - off] : 0;
        __syncthreads();
        part[t] += v;
        __syncthreads();
    }
    int run = part[t] - s;  // exclusive
    for (int i = 0; i < CH; i++) {
        int idx = base + i;
        if (idx < n) { rowptr[idx] = run; cursor[idx] = run; run += deg[idx]; }
    }
    if (t == 1023) rowptr[n] = part[1023];
}

__global__ void scatter_kernel(const int* __restrict__ src, const int* __restrict__ dst,
                               int E, int* cursor, int* csr) {
    int i = blockIdx.x * blockDim.x + threadIdx.x;
    if (i < E) {
        int d = dst[i];
        int pos = atomicAdd(&cursor[d], 1);
        csr[pos] = src[i];
    }
}

__global__ void gptr_kernel(const int* __restrict__ batch, int* gptr, int n, int B) {
    int g = threadIdx.x;
    if (g > B) return;
    int lo = 0, hi = n;
    while (lo < hi) { int mid = (lo + hi) >> 1; if (batch[mid] < g) lo = mid + 1; else hi = mid; }
    gptr[g] = lo;
}

// ---------------- SGEMM: C[M,N] = A[M,K] @ B[K,N]; K%16==0, N%128==0 ----------------
// 128x128 block tile, 256 threads, 8x8 register tile per thread.
#define BM 128
#define BN 128
#define BK 16
__global__ __launch_bounds__(256, 2) void sgemm_kernel(const float* __restrict__ A,
                                                       const float* __restrict__ B,
                                                       float* __restrict__ C,
                                                       int M, int K, int N) {
    __shared__ float As[BK][BM];
    __shared__ float Bs[BK][BN];
    int t = threadIdx.x;
    int m0 = blockIdx.y * BM;
    int n0 = blockIdx.x * BN;
    int tx = t & 15, ty = t >> 4;

    float acc[8][8];
#pragma unroll
    for (int i = 0; i < 8; i++)
#pragma unroll
        for (int j = 0; j < 8; j++) acc[i][j] = 0.f;

    for (int k0 = 0; k0 < K; k0 += BK) {
        // A tile: 128 rows x 16 cols -> As[k][m] (transposed in smem)
#pragma unroll
        for (int q = 0; q < 2; q++) {
            int idx = t * 2 + q;       // 0..511
            int row = idx >> 2;        // 0..127
            int c4 = idx & 3;          // 0..3
            int gm = m0 + row;
            float4 v = make_float4(0.f, 0.f, 0.f, 0.f);
            if (gm < M) v = *(const float4*)&A[(size_t)gm * K + k0 + c4 * 4];
            As[c4 * 4 + 0][row] = v.x;
            As[c4 * 4 + 1][row] = v.y;
            As[c4 * 4 + 2][row] = v.z;
            As[c4 * 4 + 3][row] = v.w;
        }
        // B tile: 16 rows x 128 cols
#pragma unroll
        for (int q = 0; q < 2; q++) {
            int idx = t * 2 + q;       // 0..511
            int row = idx >> 5;        // 0..15
            int c4 = idx & 31;         // 0..31
            float4 v = *(const float4*)&B[(size_t)(k0 + row) * N + n0 + c4 * 4];
            *(float4*)&Bs[row][c4 * 4] = v;
        }
        __syncthreads();
#pragma unroll
        for (int kk = 0; kk < BK; kk++) {
            float a[8], b[8];
            *(float4*)&a[0] = *(const float4*)&As[kk][ty * 8];
            *(float4*)&a[4] = *(const float4*)&As[kk][ty * 8 + 4];
            *(float4*)&b[0] = *(const float4*)&Bs[kk][tx * 8];
            *(float4*)&b[4] = *(const float4*)&Bs[kk][tx * 8 + 4];
#pragma unroll
            for (int i = 0; i < 8; i++)
#pragma unroll
                for (int j = 0; j < 8; j++) acc[i][j] += a[i] * b[j];
        }
        __syncthreads();
    }
#pragma unroll
    for (int i = 0; i < 8; i++) {
        int gm = m0 + ty * 8 + i;
        if (gm < M) {
            *(float4*)&C[(size_t)gm * N + n0 + tx * 8] =
                make_float4(acc[i][0], acc[i][1], acc[i][2], acc[i][3]);
            *(float4*)&C[(size_t)gm * N + n0 + tx * 8 + 4] =
                make_float4(acc[i][4], acc[i][5], acc[i][6], acc[i][7]);
        }
    }
}

// ---------------- per-node attention scalars ----------------
// layers 1&2: H=4, C=64; sd layout [n][8] = s0..s3,d0..d3
__global__ void sd4_kernel(const float* __restrict__ h, const float* __restrict__ asrc,
                           const float* __restrict__ adst, float* __restrict__ sd, int n) {
    int w = (blockIdx.x * blockDim.x + threadIdx.x) >> 5;
    int lane = threadIdx.x & 31;
    if (w >= n) return;
    int head = lane >> 3;
    int coff = (lane & 7) * 8;
    const float* hr = h + (size_t)w * 256 + lane * 8;
    float s = 0.f, d = 0.f;
#pragma unroll
    for (int j = 0; j < 8; j++) {
        float v = hr[j];
        s += v * asrc[head * 64 + coff + j];
        d += v * adst[head * 64 + coff + j];
    }
#pragma unroll
    for (int off = 4; off; off >>= 1) {
        s += __shfl_xor_sync(0xffffffffu, s, off);
        d += __shfl_xor_sync(0xffffffffu, d, off);
    }
    if ((lane & 7) == 0) {
        sd[(size_t)w * 8 + head] = s;
        sd[(size_t)w * 8 + 4 + head] = d;
    }
}

// layer 3: H=1, C=128; sd layout [n][2] = s,d
__global__ void sd1_kernel(const float* __restrict__ h, const float* __restrict__ asrc,
                           const float* __restrict__ adst, float* __restrict__ sd, int n) {
    int w = (blockIdx.x * blockDim.x + threadIdx.x) >> 5;
    int lane = threadIdx.x & 31;
    if (w >= n) return;
    const float* hr = h + (size_t)w * 128 + lane * 4;
    float s = 0.f, d = 0.f;
#pragma unroll
    for (int j = 0; j < 4; j++) {
        float v = hr[j];
        s += v * asrc[lane * 4 + j];
        d += v * adst[lane * 4 + j];
    }
#pragma unroll
    for (int off = 16; off; off >>= 1) {
        s += __shfl_xor_sync(0xffffffffu, s, off);
        d += __shfl_xor_sync(0xffffffffu, d, off);
    }
    if (lane == 0) {
        sd[(size_t)w * 2] = s;
        sd[(size_t)w * 2 + 1] = d;
    }
}

// ---------------- edge aggregation (warp per dst node) ----------------
__global__ void edge4_kernel(const int* __restrict__ rp, const int* __restrict__ csr,
                             const float* __restrict__ h, const float* __restrict__ sd,
                             const float* __restrict__ bias, float* __restrict__ out, int n) {
    int gw = (blockIdx.x * blockDim.x + threadIdx.x) >> 5;
    int lane = threadIdx.x & 31;
    int nw = (gridDim.x * blockDim.x) >> 5;
    for (int w = gw; w < n; w += nw) {
        int beg = rp[w];
        int deg = rp[w + 1] - beg;
        int total = deg + 1;  // implicit self loop
        float4 dn = *(const float4*)&sd[(size_t)w * 8 + 4];
        float s0 = 0.f, s1 = 0.f, s2 = 0.f, s3 = 0.f;
        for (int i = lane; i < total; i += 32) {
            int src = (i < deg) ? csr[beg + i] : w;
            float4 sv = *(const float4*)&sd[(size_t)src * 8];
            float e0 = sv.x + dn.x; e0 = e0 > 0.f ? e0 : 0.2f * e0;
            float e1 = sv.y + dn.y; e1 = e1 > 0.f ? e1 : 0.2f * e1;
            float e2 = sv.z + dn.z; e2 = e2 > 0.f ? e2 : 0.2f * e2;
            float e3 = sv.w + dn.w; e3 = e3 > 0.f ? e3 : 0.2f * e3;
            s0 += __expf(e0); s1 += __expf(e1); s2 += __expf(e2); s3 += __expf(e3);
        }
#pragma unroll
        for (int off = 16; off; off >>= 1) {
            s0 += __shfl_xor_sync(0xffffffffu, s0, off);
            s1 += __shfl_xor_sync(0xffffffffu, s1, off);
            s2 += __shfl_xor_sync(0xffffffffu, s2, off);
            s3 += __shfl_xor_sync(0xffffffffu, s3, off);
        }
        int head = lane >> 3;
        float dh = (head & 2) ? ((head & 1) ? dn.w : dn.z) : ((head & 1) ? dn.y : dn.x);
        float den = (head & 2) ? ((head & 1) ? s3 : s2) : ((head & 1) ? s1 : s0);
        float inv = 1.f / (den + 1e-16f);
        float a0 = 0, a1 = 0, a2 = 0, a3 = 0, a4 = 0, a5 = 0, a6 = 0, a7 = 0;
        const float* __restrict__ hb = h + lane * 8;
        // software-pipelined src index to expose gather address early
        int src_next = (0 < deg) ? csr[beg] : w;
        for (int i = 0; i < total; i++) {
            int src = src_next;
            src_next = (i + 1 < deg) ? csr[beg + i + 1] : w;
            float sh = sd[(size_t)src * 8 + head];
            float e = sh + dh; e = e > 0.f ? e : 0.2f * e;
            float alpha = __expf(e) * inv;
            float4 v0 = *(const float4*)(hb + (size_t)src * 256);
            float4 v1 = *(const float4*)(hb + (size_t)src * 256 + 4);
            a0 += alpha * v0.x; a1 += alpha * v0.y; a2 += alpha * v0.z; a3 += alpha * v0.w;
            a4 += alpha * v1.x; a5 += alpha * v1.y; a6 += alpha * v1.z; a7 += alpha * v1.w;
        }
        int col = lane * 8;
        float o[8] = {a0, a1, a2, a3, a4, a5, a6, a7};
#pragma unroll
        for (int j = 0; j < 8; j++) {
            float v = o[j] + bias[col + j];
            o[j] = v > 0.f ? v : expm1f(v);  // ELU
        }
        *(float4*)&out[(size_t)w * 256 + col] = make_float4(o[0], o[1], o[2], o[3]);
        *(float4*)&out[(size_t)w * 256 + col + 4] = make_float4(o[4], o[5], o[6], o[7]);
    }
}

__global__ void edge1_kernel(const int* __restrict__ rp, const int* __restrict__ csr,
                             const float* __restrict__ h, const float* __restrict__ sd,
                             const float* __restrict__ bias, float* __restrict__ out, int n) {
    int gw = (blockIdx.x * blockDim.x + threadIdx.x) >> 5;
    int lane = threadIdx.x & 31;
    int nw = (gridDim.x * blockDim.x) >> 5;
    for (int w = gw; w < n; w += nw) {
        int beg = rp[w];
        int deg = rp[w + 1] - beg;
        int total = deg + 1;
        float dn = sd[(size_t)w * 2 + 1];
        float ssum = 0.f;
        for (int i = lane; i < total; i += 32) {
            int src = (i < deg) ? csr[beg + i] : w;
            float e = sd[(size_t)src * 2] + dn;
            e = e > 0.f ? e : 0.2f * e;
            ssum += __expf(e);
        }
#pragma unroll
        for (int off = 16; off; off >>= 1) ssum += __shfl_xor_sync(0xffffffffu, ssum, off);
        float inv = 1.f / (ssum + 1e-16f);
        float a0 = 0, a1 = 0, a2 = 0, a3 = 0;
        const float* __restrict__ hb = h + lane * 4;
        int src_next = (0 < deg) ? csr[beg] : w;
        for (int i = 0; i < total; i++) {
            int src = src_next;
            src_next = (i + 1 < deg) ? csr[beg + i + 1] : w;
            float e = sd[(size_t)src * 2] + dn;
            e = e > 0.f ? e : 0.2f * e;
            float alpha = __expf(e) * inv;
            float4 v = *(const float4*)(hb + (size_t)src * 128);
            a0 += alpha * v.x; a1 += alpha * v.y; a2 += alpha * v.z; a3 += alpha * v.w;
        }
        int col = lane * 4;
        float o[4] = {a0, a1, a2, a3};
#pragma unroll
        for (int j = 0; j < 4; j++) {
            float v = o[j] + bias[col + j];
            o[j] = v > 0.f ? v : expm1f(v);
        }
        *(float4*)&out[(size_t)w * 128 + col] = make_float4(o[0], o[1], o[2], o[3]);
    }
}

// ---------------- Set2Set: one fused step (block per graph) ----------------
__device__ __forceinline__ float sigmoidf_(float x) { return 1.f / (1.f + expf(-x)); }

__global__ __launch_bounds__(128) void s2s_kernel(const float* __restrict__ x,
                                                  const int* __restrict__ gptr,
                                                  const float* __restrict__ Wih,
                                                  const float* __restrict__ Whh,
                                                  const float* __restrict__ bih,
                                                  const float* __restrict__ bhh,
                                                  float* qstar, float* hl, float* cl,
                                                  float* ebuf) {
    int b = blockIdx.x;
    int t = threadIdx.x;  // 128
    __shared__ float sq[256];
    __shared__ float shh[128];
    __shared__ float red[128];
    sq[t] = qstar[b * 256 + t];
    sq[128 + t] = qstar[b * 256 + 128 + t];
    shh[t] = hl[b * 128 + t];
    __syncthreads();

    float g[4];
#pragma unroll
    for (int gi = 0; gi < 4; gi++) {
        int row = gi * 128 + t;
        float acc = bih[row] + bhh[row];
        const float4* wi = (const float4*)&Wih[(size_t)row * 256];
#pragma unroll 8
        for (int k = 0; k < 64; k++) {
            float4 wv = wi[k];
            acc += wv.x * sq[k * 4] + wv.y * sq[k * 4 + 1] + wv.z * sq[k * 4 + 2] + wv.w * sq[k * 4 + 3];
        }
        const float4* wh = (const float4*)&Whh[(size_t)row * 128];
#pragma unroll 8
        for (int k = 0; k < 32; k++) {
            float4 wv = wh[k];
            acc += wv.x * shh[k * 4] + wv.y * shh[k * 4 + 1] + wv.z * shh[k * 4 + 2] + wv.w * shh[k * 4 + 3];
        }
        g[gi] = acc;
    }
    float cold = cl[b * 128 + t];
    float cn = sigmoidf_(g[1]) * cold + sigmoidf_(g[0]) * tanhf(g[2]);
    float hn = sigmoidf_(g[3]) * tanhf(cn);
    cl[b * 128 + t] = cn;
    hl[b * 128 + t] = hn;
    __syncthreads();      // everyone done reading shh
    shh[t] = hn;          // now holds q
    qstar[b * 256 + t] = hn;
    __syncthreads();

    int n0 = gptr[b], n1 = gptr[b + 1];
    // pass 1: e + max
    float lmax = -3.0e38f;
    for (int n = n0 + t; n < n1; n += 128) {
        const float4* xr = (const float4*)(x + (size_t)n * 128);
        float e = 0.f;
#pragma unroll 8
        for (int k = 0; k < 32; k++) {
            float4 xv = xr[k];
            e += xv.x * shh[k * 4] + xv.y * shh[k * 4 + 1] + xv.z * shh[k * 4 + 2] + xv.w * shh[k * 4 + 3];
        }
        ebuf[n] = e;
        lmax = fmaxf(lmax, e);
    }
    red[t] = lmax;
    __syncthreads();
    for (int off = 64; off; off >>= 1) {
        if (t < off) red[t] = fmaxf(red[t], red[t + off]);
        __syncthreads();
    }
    float gmax = red[0];
    __syncthreads();
    // pass 2: exp + sum
    float lsum = 0.f;
    for (int n = n0 + t; n < n1; n += 128) {
        float wv = expf(ebuf[n] - gmax);
        ebuf[n] = wv;
        lsum += wv;
    }
    red[t] = lsum;
    __syncthreads();
    for (int off = 64; off; off >>= 1) {
        if (t < off) red[t] += red[t + off];
        __syncthreads();
    }
    float inv = 1.f / (red[0] + 1e-16f);
    // pass 3: r (thread = feature, coalesced over x)
    float rj = 0.f;
    for (int n = n0; n < n1; n++) rj += ebuf[n] * x[(size_t)n * 128 + t];
    qstar[b * 256 + 128 + t] = rj * inv;
}

// ---------------- final MLPs (block per graph) ----------------
__global__ __launch_bounds__(128) void final_kernel(const float* __restrict__ qstar,
                                                    const float* __restrict__ gfeat,
                                                    const float* __restrict__ gW1, const float* __restrict__ gb1,
                                                    const float* __restrict__ gW2, const float* __restrict__ gb2,
                                                    const float* __restrict__ mW1, const float* __restrict__ mb1,
                                                    const float* __restrict__ mW2, const float* __restrict__ mb2,
                                                    float* __restrict__ out) {
    int b = blockIdx.x;
    int t = threadIdx.x;  // 128
    __shared__ float z[288];
    __shared__ float t1[64];
    __shared__ float hid[128];
    z[t] = qstar[b * 256 + t];
    z[128 + t] = qstar[b * 256 + 128 + t];
    if (t < 64) {
        float a = gb1[t];
#pragma unroll
        for (int k = 0; k < 9; k++) a += gfeat[b * 9 + k] * gW1[k * 64 + t];
        t1[t] = fmaxf(a, 0.f);
    }
    __syncthreads();
    if (t < 32) {
        float a = gb2[t];
#pragma unroll
        for (int k = 0; k < 64; k++) a += t1[k] * gW2[k * 32 + t];
        z[256 + t] = a;
    }
    __syncthreads();
    float a = mb1[t];
    for (int k = 0; k < 288; k++) a += z[k] * mW1[k * 128 + t];
    hid[t] = fmaxf(a, 0.f);
    __syncthreads();
    if (t < 4) {
        float s = mb2[t];
#pragma unroll
        for (int k = 0; k < 128; k++) s += hid[k] * mW2[k * 4 + t];
        out[b * 4 + t] = s;
    }
}

// ---------------- launch ----------------
extern "C" void kernel_launch(void* const* d_in, const int* in_sizes, int n_in,
                              void* d_out, int out_size) {
    const float* x     = (const float*)d_in[0];
    const int*   ei    = (const int*)d_in[1];
    const int*   batch = (const int*)d_in[2];
    const float* gfeat = (const float*)d_in[3];
    const float* W1 = (const float*)d_in[4];
    const float* asrc1 = (const float*)d_in[5];
    const float* adst1 = (const float*)d_in[6];
    const float* b1 = (const float*)d_in[7];
    const float* W2 = (const float*)d_in[8];
    const float* asrc2 = (const float*)d_in[9];
    const float* adst2 = (const float*)d_in[10];
    const float* b2 = (const float*)d_in[11];
    const float* W3 = (const float*)d_in[12];
    const float* asrc3 = (const float*)d_in[13];
    const float* adst3 = (const float*)d_in[14];
    const float* b3 = (const float*)d_in[15];
    const float* Wih = (const float*)d_in[16];
    const float* Whh = (const float*)d_in[17];
    const float* bih = (const float*)d_in[18];
    const float* bhh = (const float*)d_in[19];
    const float* gW1 = (const float*)d_in[20];
    const float* gb1 = (const float*)d_in[21];
    const float* gW2 = (const float*)d_in[22];
    const float* gb2 = (const float*)d_in[23];
    const float* mW1 = (const float*)d_in[24];
    const float* mb1 = (const float*)d_in[25];
    const float* mW2 = (const float*)d_in[26];
    const float* mb2 = (const float*)d_in[27];
    float* out = (float*)d_out;

    int N = in_sizes[0] / 128;   // 20000
    int E = in_sizes[1] / 2;     // 320000

    float *bufH, *bufA, *bufX, *sd, *qstar, *hl, *cl, *ebuf;
    int *deg, *rowptr, *cursor, *csr, *gptr;
    cudaGetSymbolAddress((void**)&bufH, g_bufH);
    cudaGetSymbolAddress((void**)&bufA, g_bufA);
    cudaGetSymbolAddress((void**)&bufX, g_bufX);
    cudaGetSymbolAddress((void**)&sd, g_sd);
    cudaGetSymbolAddress((void**)&qstar, g_qstar);
    cudaGetSymbolAddress((void**)&hl, g_hl);
    cudaGetSymbolAddress((void**)&cl, g_cl);
    cudaGetSymbolAddress((void**)&ebuf, g_ebuf);
    cudaGetSymbolAddress((void**)&deg, g_deg);
    cudaGetSymbolAddress((void**)&rowptr, g_rowptr);
    cudaGetSymbolAddress((void**)&cursor, g_cursor);
    cudaGetSymbolAddress((void**)&csr, g_csr);
    cudaGetSymbolAddress((void**)&gptr, g_gptr);

    int initN = N > NGRAPH * 256 ? N : NGRAPH * 256;
    init_kernel<<<(initN + 255) / 256, 256>>>(deg, qstar, hl, cl, N);
    hist_kernel<<<(E + 255) / 256, 256>>>(ei + E, E, deg);
    scan_kernel<<<1, 1024>>>(deg, rowptr, cursor, N);
    scatter_kernel<<<(E + 255) / 256, 256>>>(ei, ei + E, E, cursor, csr);
    gptr_kernel<<<1, NGRAPH + 1>>>(batch, gptr, N, NGRAPH);

    int warpBlocks = (N * 32 + 255) / 256;

    // GAT layer 1: [N,128]@[128,256]
    {
        dim3 grid(256 / BN, (N + BM - 1) / BM);
        sgemm_kernel<<<grid, 256>>>(x, W1, bufH, N, 128, 256);
    }
    sd4_kernel<<<warpBlocks, 256>>>(bufH, asrc1, adst1, sd, N);
    edge4_kernel<<<warpBlocks, 256>>>(rowptr, csr, bufH, sd, b1, bufA, N);

    // GAT layer 2: [N,256]@[256,256]
    {
        dim3 grid(256 / BN, (N + BM - 1) / BM);
        sgemm_kernel<<<grid, 256>>>(bufA, W2, bufH, N, 256, 256);
    }
    sd4_kernel<<<warpBlocks, 256>>>(bufH, asrc2, adst2, sd, N);
    edge4_kernel<<<warpBlocks, 256>>>(rowptr, csr, bufH, sd, b2, bufA, N);

    // GAT layer 3: [N,256]@[256,128], H=1
    {
        dim3 grid(128 / BN, (N + BM - 1) / BM);
        sgemm_kernel<<<grid, 256>>>(bufA, W3, bufH, N, 256, 128);
    }
    sd1_kernel<<<warpBlocks, 256>>>(bufH, asrc3, adst3, sd, N);
    edge1_kernel<<<warpBlocks, 256>>>(rowptr, csr, bufH, sd, b3, bufX, N);

    // Set2Set: 3 fused steps
    for (int s = 0; s < 3; s++)
        s2s_kernel<<<NGRAPH, 128>>>(bufX, gptr, Wih, Whh, bih, bhh, qstar, hl, cl, ebuf);

    final_kernel<<<NGRAPH, 128>>>(qstar, gfeat, gW1, gb1, gW2, gb2, mW1, mb1, mW2, mb2, out);
}

// round 7
// speedup vs baseline: 1.1717x; 1.1717x over previous
#include <cuda_runtime.h>
#include <math.h>

#define NNODES 20000
#define NEDGES 320000
#define NGRAPH 64

// ---------------- scratch (static device globals; no runtime alloc) ----------------
__device__ float g_bufH[NNODES * 256];   // GEMM output h (pre-aggregation)
__device__ float g_bufA[NNODES * 256];   // layer activations (post edge+ELU)
__device__ float g_bufX[NNODES * 128];   // layer-3 output (set2set input)
__device__ float g_sd[NNODES * 8];       // per-node attention scalars (s|d per head)
__device__ int   g_deg[NNODES];
__device__ int   g_rowptr[NNODES + 1];
__device__ int   g_cursor[NNODES];
__device__ int   g_csr[NEDGES];
__device__ int   g_gptr[NGRAPH + 1];
__device__ float g_qstar[NGRAPH * 256];
__device__ float g_hl[NGRAPH * 128];
__device__ float g_cl[NGRAPH * 128];
__device__ float g_ebuf[NNODES];

// ---------------- init ----------------
__global__ void init_kernel(int* deg, float* qs, float* hl, float* cl, int n) {
    int i = blockIdx.x * blockDim.x + threadIdx.x;
    if (i < n) deg[i] = 0;
    if (i < NGRAPH * 256) qs[i] = 0.f;
    if (i < NGRAPH * 128) { hl[i] = 0.f; cl[i] = 0.f; }
}

// ---------------- CSR build ----------------
__global__ void hist_kernel(const int* __restrict__ dst, int E, int* deg) {
    int i = blockIdx.x * blockDim.x + threadIdx.x;
    if (i < E) atomicAdd(&deg[dst[i]], 1);
}

__global__ void scan_kernel(const int* __restrict__ deg, int* rowptr, int* cursor, int n) {
    __shared__ int part[1024];
    int t = threadIdx.x;
    int CH = (n + 1023) / 1024;
    int base = t * CH;
    int s = 0;
    for (int i = 0; i < CH; i++) { int idx = base + i; if (idx < n) s += deg[idx]; }
    part[t] = s;
    __syncthreads();
    for (int off = 1; off < 1024; off <<= 1) {
        int v = (t >= off) ? part[t - off] : 0;
        __syncthreads();
        part[t] += v;
        __syncthreads();
    }
    int run = part[t] - s;  // exclusive
    for (int i = 0; i < CH; i++) {
        int idx = base + i;
        if (idx < n) { rowptr[idx] = run; cursor[idx] = run; run += deg[idx]; }
    }
    if (t == 1023) rowptr[n] = part[1023];
}

__global__ void scatter_kernel(const int* __restrict__ src, const int* __restrict__ dst,
                               int E, int* cursor, int* csr) {
    int i = blockIdx.x * blockDim.x + threadIdx.x;
    if (i < E) {
        int d = dst[i];
        int pos = atomicAdd(&cursor[d], 1);
        csr[pos] = src[i];
    }
}

__global__ void gptr_kernel(const int* __restrict__ batch, int* gptr, int n, int B) {
    int g = threadIdx.x;
    if (g > B) return;
    int lo = 0, hi = n;
    while (lo < hi) { int mid = (lo + hi) >> 1; if (batch[mid] < g) lo = mid + 1; else hi = mid; }
    gptr[g] = lo;
}

// ---------------- SGEMM (double-buffered) + optional fused sd epilogue ----------------
// C[M,N] = A[M,K] @ B[K,N]; K%16==0, N%64==0.
// 128x64 tile, 256 threads, 8 rows x 4 cols per thread.
// If asrc != nullptr: BN==64 column block == one head; epilogue computes
// s = h . asrc[head], d = h . adst[head] per row (16-lane shfl reduce), writes sd[row*8 + head(+4)].
#define BM 128
#define BN 64
#define BK 16
__global__ __launch_bounds__(256) void sgemm_sd_kernel(const float* __restrict__ A,
                                                       const float* __restrict__ B,
                                                       float* __restrict__ C,
                                                       int M, int K, int N,
                                                       const float* __restrict__ asrc,
                                                       const float* __restrict__ adst,
                                                       float* __restrict__ sd) {
    __shared__ float As[2][BK][BM];
    __shared__ float Bs[2][BK][BN];
    int t = threadIdx.x;
    int m0 = blockIdx.y * BM;
    int n0 = blockIdx.x * BN;
    int tx = t & 15, ty = t >> 4;
    int brow = t >> 4, bc4 = t & 15;

    float4 aReg[2];
    float4 bReg;

    auto ldTiles = [&](int k0) {
#pragma unroll
        for (int q = 0; q < 2; q++) {
            int idx = t * 2 + q;       // 0..511
            int row = idx >> 2;        // 0..127
            int c4 = idx & 3;          // 0..3
            int gm = m0 + row;
            aReg[q] = (gm < M) ? *(const float4*)&A[(size_t)gm * K + k0 + c4 * 4]
                               : make_float4(0.f, 0.f, 0.f, 0.f);
        }
        bReg = *(const float4*)&B[(size_t)(k0 + brow) * N + n0 + bc4 * 4];
    };
    auto stTiles = [&](int buf) {
#pragma unroll
        for (int q = 0; q < 2; q++) {
            int idx = t * 2 + q;
            int row = idx >> 2;
            int c4 = idx & 3;
            As[buf][c4 * 4 + 0][row] = aReg[q].x;
            As[buf][c4 * 4 + 1][row] = aReg[q].y;
            As[buf][c4 * 4 + 2][row] = aReg[q].z;
            As[buf][c4 * 4 + 3][row] = aReg[q].w;
        }
        *(float4*)&Bs[buf][brow][bc4 * 4] = bReg;
    };

    float acc[8][4];
#pragma unroll
    for (int i = 0; i < 8; i++)
#pragma unroll
        for (int j = 0; j < 4; j++) acc[i][j] = 0.f;

    ldTiles(0);
    stTiles(0);
    __syncthreads();

    int buf = 0;
    for (int k0 = 0; k0 < K; k0 += BK) {
        int kn = k0 + BK;
        if (kn < K) ldTiles(kn);       // issue next gmem loads before compute
#pragma unroll
        for (int kk = 0; kk < BK; kk++) {
            float a[8], b[4];
            *(float4*)&a[0] = *(const float4*)&As[buf][kk][ty * 8];
            *(float4*)&a[4] = *(const float4*)&As[buf][kk][ty * 8 + 4];
            *(float4*)&b[0] = *(const float4*)&Bs[buf][kk][tx * 4];
#pragma unroll
            for (int i = 0; i < 8; i++)
#pragma unroll
                for (int j = 0; j < 4; j++) acc[i][j] += a[i] * b[j];
        }
        if (kn < K) stTiles(buf ^ 1);
        __syncthreads();
        buf ^= 1;
    }

#pragma unroll
    for (int i = 0; i < 8; i++) {
        int gm = m0 + ty * 8 + i;
        if (gm < M) {
            *(float4*)&C[(size_t)gm * N + n0 + tx * 4] =
                make_float4(acc[i][0], acc[i][1], acc[i][2], acc[i][3]);
        }
    }

    if (asrc != nullptr) {
        int head = blockIdx.x;   // BN==64 -> column block == head
        float as[4], ad[4];
#pragma unroll
        for (int j = 0; j < 4; j++) {
            as[j] = asrc[head * 64 + tx * 4 + j];
            ad[j] = adst[head * 64 + tx * 4 + j];
        }
#pragma unroll
        for (int i = 0; i < 8; i++) {
            float s = 0.f, d = 0.f;
#pragma unroll
            for (int j = 0; j < 4; j++) {
                s += acc[i][j] * as[j];
                d += acc[i][j] * ad[j];
            }
#pragma unroll
            for (int off = 8; off; off >>= 1) {
                s += __shfl_xor_sync(0xffffffffu, s, off);
                d += __shfl_xor_sync(0xffffffffu, d, off);
            }
            int gm = m0 + ty * 8 + i;
            if (tx == 0 && gm < M) {
                sd[(size_t)gm * 8 + head] = s;
                sd[(size_t)gm * 8 + 4 + head] = d;
            }
        }
    }
}

// ---------------- layer-3 attention scalars: H=1, C=128; sd layout [n][2] = s,d ----------------
__global__ void sd1_kernel(const float* __restrict__ h, const float* __restrict__ asrc,
                           const float* __restrict__ adst, float* __restrict__ sd, int n) {
    int w = (blockIdx.x * blockDim.x + threadIdx.x) >> 5;
    int lane = threadIdx.x & 31;
    if (w >= n) return;
    const float* hr = h + (size_t)w * 128 + lane * 4;
    float s = 0.f, d = 0.f;
#pragma unroll
    for (int j = 0; j < 4; j++) {
        float v = hr[j];
        s += v * asrc[lane * 4 + j];
        d += v * adst[lane * 4 + j];
    }
#pragma unroll
    for (int off = 16; off; off >>= 1) {
        s += __shfl_xor_sync(0xffffffffu, s, off);
        d += __shfl_xor_sync(0xffffffffu, d, off);
    }
    if (lane == 0) {
        sd[(size_t)w * 2] = s;
        sd[(size_t)w * 2 + 1] = d;
    }
}

// ---------------- edge aggregation (warp per dst node) ----------------
__global__ void edge4_kernel(const int* __restrict__ rp, const int* __restrict__ csr,
                             const float* __restrict__ h, const float* __restrict__ sd,
                             const float* __restrict__ bias, float* __restrict__ out, int n) {
    int gw = (blockIdx.x * blockDim.x + threadIdx.x) >> 5;
    int lane = threadIdx.x & 31;
    int nw = (gridDim.x * blockDim.x) >> 5;
    for (int w = gw; w < n; w += nw) {
        int beg = rp[w];
        int deg = rp[w + 1] - beg;
        int total = deg + 1;  // implicit self loop
        float4 dn = *(const float4*)&sd[(size_t)w * 8 + 4];
        float s0 = 0.f, s1 = 0.f, s2 = 0.f, s3 = 0.f;
        for (int i = lane; i < total; i += 32) {
            int src = (i < deg) ? csr[beg + i] : w;
            float4 sv = *(const float4*)&sd[(size_t)src * 8];
            float e0 = sv.x + dn.x; e0 = e0 > 0.f ? e0 : 0.2f * e0;
            float e1 = sv.y + dn.y; e1 = e1 > 0.f ? e1 : 0.2f * e1;
            float e2 = sv.z + dn.z; e2 = e2 > 0.f ? e2 : 0.2f * e2;
            float e3 = sv.w + dn.w; e3 = e3 > 0.f ? e3 : 0.2f * e3;
            s0 += __expf(e0); s1 += __expf(e1); s2 += __expf(e2); s3 += __expf(e3);
        }
#pragma unroll
        for (int off = 16; off; off >>= 1) {
            s0 += __shfl_xor_sync(0xffffffffu, s0, off);
            s1 += __shfl_xor_sync(0xffffffffu, s1, off);
            s2 += __shfl_xor_sync(0xffffffffu, s2, off);
            s3 += __shfl_xor_sync(0xffffffffu, s3, off);
        }
        int head = lane >> 3;
        float dh = (head & 2) ? ((head & 1) ? dn.w : dn.z) : ((head & 1) ? dn.y : dn.x);
        float den = (head & 2) ? ((head & 1) ? s3 : s2) : ((head & 1) ? s1 : s0);
        float inv = 1.f / (den + 1e-16f);
        float a0 = 0, a1 = 0, a2 = 0, a3 = 0, a4 = 0, a5 = 0, a6 = 0, a7 = 0;
        const float* __restrict__ hb = h + lane * 8;
        // software-pipelined src index to expose gather address early
        int src_next = (0 < deg) ? csr[beg] : w;
        for (int i = 0; i < total; i++) {
            int src = src_next;
            src_next = (i + 1 < deg) ? csr[beg + i + 1] : w;
            float sh = sd[(size_t)src * 8 + head];
            float e = sh + dh; e = e > 0.f ? e : 0.2f * e;
            float alpha = __expf(e) * inv;
            float4 v0 = *(const float4*)(hb + (size_t)src * 256);
            float4 v1 = *(const float4*)(hb + (size_t)src * 256 + 4);
            a0 += alpha * v0.x; a1 += alpha * v0.y; a2 += alpha * v0.z; a3 += alpha * v0.w;
            a4 += alpha * v1.x; a5 += alpha * v1.y; a6 += alpha * v1.z; a7 += alpha * v1.w;
        }
        int col = lane * 8;
        float o[8] = {a0, a1, a2, a3, a4, a5, a6, a7};
#pragma unroll
        for (int j = 0; j < 8; j++) {
            float v = o[j] + bias[col + j];
            o[j] = v > 0.f ? v : expm1f(v);  // ELU
        }
        *(float4*)&out[(size_t)w * 256 + col] = make_float4(o[0], o[1], o[2], o[3]);
        *(float4*)&out[(size_t)w * 256 + col + 4] = make_float4(o[4], o[5], o[6], o[7]);
    }
}

__global__ void edge1_kernel(const int* __restrict__ rp, const int* __restrict__ csr,
                             const float* __restrict__ h, const float* __restrict__ sd,
                             const float* __restrict__ bias, float* __restrict__ out, int n) {
    int gw = (blockIdx.x * blockDim.x + threadIdx.x) >> 5;
    int lane = threadIdx.x & 31;
    int nw = (gridDim.x * blockDim.x) >> 5;
    for (int w = gw; w < n; w += nw) {
        int beg = rp[w];
        int deg = rp[w + 1] - beg;
        int total = deg + 1;
        float dn = sd[(size_t)w * 2 + 1];
        float ssum = 0.f;
        for (int i = lane; i < total; i += 32) {
            int src = (i < deg) ? csr[beg + i] : w;
            float e = sd[(size_t)src * 2] + dn;
            e = e > 0.f ? e : 0.2f * e;
            ssum += __expf(e);
        }
#pragma unroll
        for (int off = 16; off; off >>= 1) ssum += __shfl_xor_sync(0xffffffffu, ssum, off);
        float inv = 1.f / (ssum + 1e-16f);
        float a0 = 0, a1 = 0, a2 = 0, a3 = 0;
        const float* __restrict__ hb = h + lane * 4;
        int src_next = (0 < deg) ? csr[beg] : w;
        for (int i = 0; i < total; i++) {
            int src = src_next;
            src_next = (i + 1 < deg) ? csr[beg + i + 1] : w;
            float e = sd[(size_t)src * 2] + dn;
            e = e > 0.f ? e : 0.2f * e;
            float alpha = __expf(e) * inv;
            float4 v = *(const float4*)(hb + (size_t)src * 128);
            a0 += alpha * v.x; a1 += alpha * v.y; a2 += alpha * v.z; a3 += alpha * v.w;
        }
        int col = lane * 4;
        float o[4] = {a0, a1, a2, a3};
#pragma unroll
        for (int j = 0; j < 4; j++) {
            float v = o[j] + bias[col + j];
            o[j] = v > 0.f ? v : expm1f(v);
        }
        *(float4*)&out[(size_t)w * 128 + col] = make_float4(o[0], o[1], o[2], o[3]);
    }
}

// ---------------- Set2Set: one fused step (block per graph) ----------------
__device__ __forceinline__ float sigmoidf_(float x) { return 1.f / (1.f + expf(-x)); }

__global__ __launch_bounds__(128) void s2s_kernel(const float* __restrict__ x,
                                                  const int* __restrict__ gptr,
                                                  const float* __restrict__ Wih,
                                                  const float* __restrict__ Whh,
                                                  const float* __restrict__ bih,
                                                  const float* __restrict__ bhh,
                                                  float* qstar, float* hl, float* cl,
                                                  float* ebuf) {
    int b = blockIdx.x;
    int t = threadIdx.x;  // 128
    __shared__ float sq[256];
    __shared__ float shh[128];
    __shared__ float red[128];
    sq[t] = qstar[b * 256 + t];
    sq[128 + t] = qstar[b * 256 + 128 + t];
    shh[t] = hl[b * 128 + t];
    __syncthreads();

    float g[4];
#pragma unroll
    for (int gi = 0; gi < 4; gi++) {
        int row = gi * 128 + t;
        float acc = bih[row] + bhh[row];
        const float4* wi = (const float4*)&Wih[(size_t)row * 256];
#pragma unroll 8
        for (int k = 0; k < 64; k++) {
            float4 wv = wi[k];
            acc += wv.x * sq[k * 4] + wv.y * sq[k * 4 + 1] + wv.z * sq[k * 4 + 2] + wv.w * sq[k * 4 + 3];
        }
        const float4* wh = (const float4*)&Whh[(size_t)row * 128];
#pragma unroll 8
        for (int k = 0; k < 32; k++) {
            float4 wv = wh[k];
            acc += wv.x * shh[k * 4] + wv.y * shh[k * 4 + 1] + wv.z * shh[k * 4 + 2] + wv.w * shh[k * 4 + 3];
        }
        g[gi] = acc;
    }
    float cold = cl[b * 128 + t];
    float cn = sigmoidf_(g[1]) * cold + sigmoidf_(g[0]) * tanhf(g[2]);
    float hn = sigmoidf_(g[3]) * tanhf(cn);
    cl[b * 128 + t] = cn;
    hl[b * 128 + t] = hn;
    __syncthreads();      // everyone done reading shh
    shh[t] = hn;          // now holds q
    qstar[b * 256 + t] = hn;
    __syncthreads();

    int n0 = gptr[b], n1 = gptr[b + 1];
    // pass 1: e + max
    float lmax = -3.0e38f;
    for (int n = n0 + t; n < n1; n += 128) {
        const float4* xr = (const float4*)(x + (size_t)n * 128);
        float e = 0.f;
#pragma unroll 8
        for (int k = 0; k < 32; k++) {
            float4 xv = xr[k];
            e += xv.x * shh[k * 4] + xv.y * shh[k * 4 + 1] + xv.z * shh[k * 4 + 2] + xv.w * shh[k * 4 + 3];
        }
        ebuf[n] = e;
        lmax = fmaxf(lmax, e);
    }
    red[t] = lmax;
    __syncthreads();
    for (int off = 64; off; off >>= 1) {
        if (t < off) red[t] = fmaxf(red[t], red[t + off]);
        __syncthreads();
    }
    float gmax = red[0];
    __syncthreads();
    // pass 2: exp + sum
    float lsum = 0.f;
    for (int n = n0 + t; n < n1; n += 128) {
        float wv = expf(ebuf[n] - gmax);
        ebuf[n] = wv;
        lsum += wv;
    }
    red[t] = lsum;
    __syncthreads();
    for (int off = 64; off; off >>= 1) {
        if (t < off) red[t] += red[t + off];
        __syncthreads();
    }
    float inv = 1.f / (red[0] + 1e-16f);
    // pass 3: r (thread = feature, coalesced over x)
    float rj = 0.f;
    for (int n = n0; n < n1; n++) rj += ebuf[n] * x[(size_t)n * 128 + t];
    qstar[b * 256 + 128 + t] = rj * inv;
}

// ---------------- final MLPs (block per graph) ----------------
__global__ __launch_bounds__(128) void final_kernel(const float* __restrict__ qstar,
                                                    const float* __restrict__ gfeat,
                                                    const float* __restrict__ gW1, const float* __restrict__ gb1,
                                                    const float* __restrict__ gW2, const float* __restrict__ gb2,
                                                    const float* __restrict__ mW1, const float* __restrict__ mb1,
                                                    const float* __restrict__ mW2, const float* __restrict__ mb2,
                                                    float* __restrict__ out) {
    int b = blockIdx.x;
    int t = threadIdx.x;  // 128
    __shared__ float z[288];
    __shared__ float t1[64];
    __shared__ float hid[128];
    z[t] = qstar[b * 256 + t];
    z[128 + t] = qstar[b * 256 + 128 + t];
    if (t < 64) {
        float a = gb1[t];
#pragma unroll
        for (int k = 0; k < 9; k++) a += gfeat[b * 9 + k] * gW1[k * 64 + t];
        t1[t] = fmaxf(a, 0.f);
    }
    __syncthreads();
    if (t < 32) {
        float a = gb2[t];
#pragma unroll
        for (int k = 0; k < 64; k++) a += t1[k] * gW2[k * 32 + t];
        z[256 + t] = a;
    }
    __syncthreads();
    float a = mb1[t];
    for (int k = 0; k < 288; k++) a += z[k] * mW1[k * 128 + t];
    hid[t] = fmaxf(a, 0.f);
    __syncthreads();
    if (t < 4) {
        float s = mb2[t];
#pragma unroll
        for (int k = 0; k < 128; k++) s += hid[k] * mW2[k * 4 + t];
        out[b * 4 + t] = s;
    }
}

// ---------------- launch ----------------
extern "C" void kernel_launch(void* const* d_in, const int* in_sizes, int n_in,
                              void* d_out, int out_size) {
    const float* x     = (const float*)d_in[0];
    const int*   ei    = (const int*)d_in[1];
    const int*   batch = (const int*)d_in[2];
    const float* gfeat = (const float*)d_in[3];
    const float* W1 = (const float*)d_in[4];
    const float* asrc1 = (const float*)d_in[5];
    const float* adst1 = (const float*)d_in[6];
    const float* b1 = (const float*)d_in[7];
    const float* W2 = (const float*)d_in[8];
    const float* asrc2 = (const float*)d_in[9];
    const float* adst2 = (const float*)d_in[10];
    const float* b2 = (const float*)d_in[11];
    const float* W3 = (const float*)d_in[12];
    const float* asrc3 = (const float*)d_in[13];
    const float* adst3 = (const float*)d_in[14];
    const float* b3 = (const float*)d_in[15];
    const float* Wih = (const float*)d_in[16];
    const float* Whh = (const float*)d_in[17];
    const float* bih = (const float*)d_in[18];
    const float* bhh = (const float*)d_in[19];
    const float* gW1 = (const float*)d_in[20];
    const float* gb1 = (const float*)d_in[21];
    const float* gW2 = (const float*)d_in[22];
    const float* gb2 = (const float*)d_in[23];
    const float* mW1 = (const float*)d_in[24];
    const float* mb1 = (const float*)d_in[25];
    const float* mW2 = (const float*)d_in[26];
    const float* mb2 = (const float*)d_in[27];
    float* out = (float*)d_out;

    int N = in_sizes[0] / 128;   // 20000
    int E = in_sizes[1] / 2;     // 320000

    float *bufH, *bufA, *bufX, *sd, *qstar, *hl, *cl, *ebuf;
    int *deg, *rowptr, *cursor, *csr, *gptr;
    cudaGetSymbolAddress((void**)&bufH, g_bufH);
    cudaGetSymbolAddress((void**)&bufA, g_bufA);
    cudaGetSymbolAddress((void**)&bufX, g_bufX);
    cudaGetSymbolAddress((void**)&sd, g_sd);
    cudaGetSymbolAddress((void**)&qstar, g_qstar);
    cudaGetSymbolAddress((void**)&hl, g_hl);
    cudaGetSymbolAddress((void**)&cl, g_cl);
    cudaGetSymbolAddress((void**)&ebuf, g_ebuf);
    cudaGetSymbolAddress((void**)&deg, g_deg);
    cudaGetSymbolAddress((void**)&rowptr, g_rowptr);
    cudaGetSymbolAddress((void**)&cursor, g_cursor);
    cudaGetSymbolAddress((void**)&csr, g_csr);
    cudaGetSymbolAddress((void**)&gptr, g_gptr);

    int initN = N > NGRAPH * 256 ? N : NGRAPH * 256;
    init_kernel<<<(initN + 255) / 256, 256>>>(deg, qstar, hl, cl, N);
    hist_kernel<<<(E + 255) / 256, 256>>>(ei + E, E, deg);
    scan_kernel<<<1, 1024>>>(deg, rowptr, cursor, N);
    scatter_kernel<<<(E + 255) / 256, 256>>>(ei, ei + E, E, cursor, csr);
    gptr_kernel<<<1, NGRAPH + 1>>>(batch, gptr, N, NGRAPH);

    int warpBlocks = (N * 32 + 255) / 256;

    // GAT layer 1: [N,128]@[128,256] + fused sd epilogue
    {
        dim3 grid(256 / BN, (N + BM - 1) / BM);
        sgemm_sd_kernel<<<grid, 256>>>(x, W1, bufH, N, 128, 256, asrc1, adst1, sd);
    }
    edge4_kernel<<<warpBlocks, 256>>>(rowptr, csr, bufH, sd, b1, bufA, N);

    // GAT layer 2: [N,256]@[256,256] + fused sd epilogue
    {
        dim3 grid(256 / BN, (N + BM - 1) / BM);
        sgemm_sd_kernel<<<grid, 256>>>(bufA, W2, bufH, N, 256, 256, asrc2, adst2, sd);
    }
    edge4_kernel<<<warpBlocks, 256>>>(rowptr, csr, bufH, sd, b2, bufA, N);

    // GAT layer 3: [N,256]@[256,128], H=1 (sd fused off; sd1 kernel computes full 128-dot)
    {
        dim3 grid(128 / BN, (N + BM - 1) / BM);
        sgemm_sd_kernel<<<grid, 256>>>(bufA, W3, bufH, N, 256, 128, nullptr, nullptr, nullptr);
    }
    sd1_kernel<<<warpBlocks, 256>>>(bufH, asrc3, adst3, sd, N);
    edge1_kernel<<<warpBlocks, 256>>>(rowptr, csr, bufH, sd, b3, bufX, N);

    // Set2Set: 3 fused steps
    for (int s = 0; s < 3; s++)
        s2s_kernel<<<NGRAPH, 128>>>(bufX, gptr, Wih, Whh, bih, bhh, qstar, hl, cl, ebuf);

    final_kernel<<<NGRAPH, 128>>>(qstar, gfeat, gW1, gb1, gW2, gb2, mW1, mb1, mW2, mb2, out);
}